// round 1
// baseline (speedup 1.0000x reference)
#include <cuda_runtime.h>
#include <cuda_bf16.h>
#include <stdint.h>

#define MAXC 8
#define REC_CAP 2097152

// Accumulator layout (doubles):
// [0, MAXC*7): per-chain: 0..2 pocket-pos sum, 3..5 ref-poc sum, 6 count
// then: rec pos sum (3), rec chain counts (MAXC), F sum (3), T sum (3)
#define ACC_CH(c,f) ((c)*7+(f))
#define ACC_RSUM (MAXC*7)
#define ACC_RCNT (MAXC*7+3)
#define ACC_F    (MAXC*7+3+MAXC)
#define ACC_T    (MAXC*7+6+MAXC)
#define ACC_N    (MAXC*7+9+MAXC)

__device__ double g_acc[ACC_N];
__device__ float  g_bt[MAXC*3];   // per-chain best periodic translation
__device__ float  g_origin[3];    // rec_origin
__device__ float  g_fm[3];        // F_mean
__device__ float  g_tm[3];        // torque_mean
__device__ float4 g_recpos[REC_CAP];  // cached positions[rec_indices]

__device__ __forceinline__ float warp_sum(float v) {
#pragma unroll
    for (int o = 16; o; o >>= 1) v += __shfl_down_sync(0xffffffffu, v, o);
    return v;
}

__global__ void k_init() {
    int t = threadIdx.x;
    if (t < ACC_N) g_acc[t] = 0.0;
}

// Pass 1: per-chain pocket COM sums. NOTE: faithfully reproduces the
// reference bug — pocket positions gathered from GLOBAL positions with
// poc_indices (indices into the rec array), not from rec_pos.
__global__ void k_poc_com(const float* __restrict__ pos,
                          const float* __restrict__ refp,
                          const int* __restrict__ pidx,
                          const int* __restrict__ pcid,
                          int n_poc, const int* __restrict__ nch) {
    __shared__ float s[MAXC * 7];
    int C = nch ? *nch : 4;
    if (C > MAXC) C = MAXC;
    for (int t = threadIdx.x; t < C * 7; t += blockDim.x) s[t] = 0.f;
    __syncthreads();

    int j = blockIdx.x * blockDim.x + threadIdx.x;
    if (j < n_poc) {
        int c = __ldg(pcid + j);
        int p = __ldg(pidx + j);
        float gx = __ldg(pos + 3 * p), gy = __ldg(pos + 3 * p + 1), gz = __ldg(pos + 3 * p + 2);
        float rx = __ldg(refp + 3 * j), ry = __ldg(refp + 3 * j + 1), rz = __ldg(refp + 3 * j + 2);
        int b = c * 7;
        atomicAdd(&s[b + 0], gx);
        atomicAdd(&s[b + 1], gy);
        atomicAdd(&s[b + 2], gz);
        atomicAdd(&s[b + 3], rx);
        atomicAdd(&s[b + 4], ry);
        atomicAdd(&s[b + 5], rz);
        atomicAdd(&s[b + 6], 1.f);
    }
    __syncthreads();
    for (int t = threadIdx.x; t < C * 7; t += blockDim.x) {
        float v = s[t];
        if (v != 0.f) atomicAdd(&g_acc[t], (double)v);
    }
}

// Pass 2: gather positions[rec_indices], cache to g_recpos, sum positions,
// count rec atoms per chain.
__global__ void k_rec_sum(const float* __restrict__ pos,
                          const int* __restrict__ rec_idx,
                          const int* __restrict__ cid,
                          int n_rec, const int* __restrict__ nch) {
    __shared__ float s[3 + MAXC];
    int C = nch ? *nch : 4;
    if (C > MAXC) C = MAXC;
    for (int t = threadIdx.x; t < 3 + C; t += blockDim.x) s[t] = 0.f;
    __syncthreads();

    int i = blockIdx.x * blockDim.x + threadIdx.x;
    bool v = i < n_rec;
    float px = 0.f, py = 0.f, pz = 0.f;
    int c = 0;
    if (v) {
        int r = __ldg(rec_idx + i);
        px = __ldg(pos + 3 * r);
        py = __ldg(pos + 3 * r + 1);
        pz = __ldg(pos + 3 * r + 2);
        c = __ldg(cid + i);
        if (i < REC_CAP) g_recpos[i] = make_float4(px, py, pz, 0.f);
    }
    px = warp_sum(px); py = warp_sum(py); pz = warp_sum(pz);
    unsigned lane = threadIdx.x & 31u;
    if (lane == 0) {
        atomicAdd(&s[0], px);
        atomicAdd(&s[1], py);
        atomicAdd(&s[2], pz);
    }
#pragma unroll
    for (int cc = 0; cc < MAXC; ++cc) {
        if (cc >= C) break;
        unsigned m = __ballot_sync(0xffffffffu, v && (c == cc));
        if (lane == 0 && m) atomicAdd(&s[3 + cc], (float)__popc(m));
    }
    __syncthreads();
    for (int t = threadIdx.x; t < 3 + C; t += blockDim.x) {
        float val = s[t];
        if (val != 0.f) {
            int dst = (t < 3) ? (ACC_RSUM + t) : (ACC_RCNT + (t - 3));
            atomicAdd(&g_acc[dst], (double)val);
        }
    }
}

// Tiny kernel: best periodic translation per chain + rec_origin.
__global__ void k_setup(const float* __restrict__ box,
                        const int* __restrict__ nch, int n_rec) {
    if (threadIdx.x != 0 || blockIdx.x != 0) return;
    int C = nch ? *nch : 4;
    if (C > MAXC) C = MAXC;
    float r0x = box[0], r0y = box[1], r0z = box[2];
    float r1x = box[3], r1y = box[4], r1z = box[5];
    float r2x = box[6], r2y = box[7], r2z = box[8];
    float i0 = 1.f / box[0], i1 = 1.f / box[4], i2 = 1.f / box[8];
    double txa = 0.0, tya = 0.0, tza = 0.0;
    for (int c = 0; c < C; ++c) {
        double cnt = g_acc[ACC_CH(c, 6)];
        double inv = (cnt > 0.0) ? 1.0 / cnt : 0.0;
        float pcx = (float)(g_acc[ACC_CH(c, 0)] * inv);
        float pcy = (float)(g_acc[ACC_CH(c, 1)] * inv);
        float pcz = (float)(g_acc[ACC_CH(c, 2)] * inv);
        float rcx = (float)(g_acc[ACC_CH(c, 3)] * inv);
        float rcy = (float)(g_acc[ACC_CH(c, 4)] * inv);
        float rcz = (float)(g_acc[ACC_CH(c, 5)] * inv);
        // delta = ref_com - poc_com, reduced sequentially (z, y, x) as reference
        float dx = rcx - pcx, dy = rcy - pcy, dz = rcz - pcz;
        float s3 = rintf(dz * i2);
        dx -= s3 * r2x; dy -= s3 * r2y; dz -= s3 * r2z;
        float s2 = rintf(dy * i1);
        dx -= s2 * r1x; dy -= s2 * r1y; dz -= s2 * r1z;
        float s1 = rintf(dx * i0);
        float tx = s1 * r0x + s2 * r1x + s3 * r2x;
        float ty = s1 * r0y + s2 * r1y + s3 * r2y;
        float tz = s1 * r0z + s2 * r1z + s3 * r2z;
        g_bt[c * 3 + 0] = tx;
        g_bt[c * 3 + 1] = ty;
        g_bt[c * 3 + 2] = tz;
        double rc = g_acc[ACC_RCNT + c];
        txa += rc * (double)tx;
        tya += rc * (double)ty;
        tza += rc * (double)tz;
    }
    double invR = 1.0 / (double)n_rec;
    g_origin[0] = (float)((g_acc[ACC_RSUM + 0] + txa) * invR);
    g_origin[1] = (float)((g_acc[ACC_RSUM + 1] + tya) * invR);
    g_origin[2] = (float)((g_acc[ACC_RSUM + 2] + tza) * invR);
}

// Pass 3: pocket forces + torques -> global sums.
__global__ void k_poc_force(const float* __restrict__ refp,
                            const int* __restrict__ pidx,
                            const int* __restrict__ pcid,
                            const float* __restrict__ kptr,
                            int n_poc) {
    __shared__ float s[6];
    if (threadIdx.x < 6) s[threadIdx.x] = 0.f;
    __syncthreads();

    int j = blockIdx.x * blockDim.x + threadIdx.x;
    bool v = j < n_poc;
    float Fx = 0.f, Fy = 0.f, Fz = 0.f, Tx = 0.f, Ty = 0.f, Tz = 0.f;
    if (v) {
        int p = __ldg(pidx + j);
        int c = __ldg(pcid + j);
        float4 rp = g_recpos[p];
        float bx = g_bt[c * 3 + 0], by = g_bt[c * 3 + 1], bz = g_bt[c * 3 + 2];
        float ppx = rp.x + bx, ppy = rp.y + by, ppz = rp.z + bz;
        float k2 = -2.f * __ldg(kptr);
        Fx = k2 * (ppx - __ldg(refp + 3 * j));
        Fy = k2 * (ppy - __ldg(refp + 3 * j + 1));
        Fz = k2 * (ppz - __ldg(refp + 3 * j + 2));
        float cx = ppx - g_origin[0];
        float cy = ppy - g_origin[1];
        float cz = ppz - g_origin[2];
        Tx = cy * Fz - cz * Fy;
        Ty = cz * Fx - cx * Fz;
        Tz = cx * Fy - cy * Fx;
    }
    Fx = warp_sum(Fx); Fy = warp_sum(Fy); Fz = warp_sum(Fz);
    Tx = warp_sum(Tx); Ty = warp_sum(Ty); Tz = warp_sum(Tz);
    if ((threadIdx.x & 31u) == 0) {
        atomicAdd(&s[0], Fx); atomicAdd(&s[1], Fy); atomicAdd(&s[2], Fz);
        atomicAdd(&s[3], Tx); atomicAdd(&s[4], Ty); atomicAdd(&s[5], Tz);
    }
    __syncthreads();
    if (threadIdx.x < 6) {
        float val = s[threadIdx.x];
        if (val != 0.f) {
            int dst = (threadIdx.x < 3) ? (ACC_F + threadIdx.x) : (ACC_T + threadIdx.x - 3);
            atomicAdd(&g_acc[dst], (double)val);
        }
    }
}

__global__ void k_finalize(int n_rec) {
    int t = threadIdx.x;
    if (t < 3) {
        double invR = 1.0 / (double)n_rec;
        g_fm[t] = (float)(g_acc[ACC_F + t] * invR);
        g_tm[t] = (float)(g_acc[ACC_T + t] * invR);
    }
}

// Pass 4: scatter final forces into output.
__global__ void k_scatter(const int* __restrict__ rec_idx,
                          const int* __restrict__ cid,
                          float* __restrict__ out,
                          int n_rec, int base) {
    int i = blockIdx.x * blockDim.x + threadIdx.x;
    if (i >= n_rec || i >= REC_CAP) return;
    float4 rp = g_recpos[i];
    int c = __ldg(cid + i);
    int r = __ldg(rec_idx + i);
    float cx = rp.x + g_bt[c * 3 + 0] - g_origin[0];
    float cy = rp.y + g_bt[c * 3 + 1] - g_origin[1];
    float cz = rp.z + g_bt[c * 3 + 2] - g_origin[2];
    float rsq = cx * cx + cy * cy + cz * cz;
    float inv = 1.f / rsq;
    float tmx = g_tm[0], tmy = g_tm[1], tmz = g_tm[2];
    float Fx = g_fm[0] + (tmy * cz - tmz * cy) * inv;
    float Fy = g_fm[1] + (tmz * cx - tmx * cz) * inv;
    float Fz = g_fm[2] + (tmx * cy - tmy * cx) * inv;
    long long o = (long long)base + 3LL * (long long)r;
    out[o + 0] = Fx;
    out[o + 1] = Fy;
    out[o + 2] = Fz;
}

extern "C" void kernel_launch(void* const* d_in, const int* in_sizes, int n_in,
                              void* d_out, int out_size) {
    const float* positions = (const float*)d_in[0];
    const float* box       = (const float*)d_in[1];
    const float* ref_poc   = (const float*)d_in[2];
    const float* kptr      = (const float*)d_in[3];
    const int*   rec_idx   = (const int*)d_in[4];
    const int*   poc_idx   = (const int*)d_in[5];
    const int*   cid       = (const int*)d_in[6];
    const int*   pcid      = (const int*)d_in[7];
    const int*   nch       = (n_in >= 9) ? (const int*)d_in[8] : nullptr;

    int n_atoms = in_sizes[0] / 3;
    int n_rec   = in_sizes[4];
    int n_poc   = in_sizes[5];
    int base = out_size - 3 * n_atoms;
    if (base < 0) base = 0;

    const int TPB = 256;

    // Zero the full output (covers leading energy scalar if present).
    cudaMemsetAsync(d_out, 0, (size_t)out_size * sizeof(float));
    k_init<<<1, 128>>>();
    k_rec_sum<<<(n_rec + TPB - 1) / TPB, TPB>>>(positions, rec_idx, cid, n_rec, nch);
    k_poc_com<<<(n_poc + TPB - 1) / TPB, TPB>>>(positions, ref_poc, poc_idx, pcid, n_poc, nch);
    k_setup<<<1, 32>>>(box, nch, n_rec);
    k_poc_force<<<(n_poc + TPB - 1) / TPB, TPB>>>(ref_poc, poc_idx, pcid, kptr, n_poc);
    k_finalize<<<1, 32>>>(n_rec);
    k_scatter<<<(n_rec + TPB - 1) / TPB, TPB>>>(rec_idx, cid, (float*)d_out, n_rec, base);
}

// round 2
// speedup vs baseline: 1.0741x; 1.0741x over previous
#include <cuda_runtime.h>
#include <cuda_bf16.h>
#include <stdint.h>

#define MAXC 8
#define REC_CAP 2097152

// Accumulator layout (doubles):
// per chain c (7): 0..2 poc_glob sum, 3..5 ref sum, 6 count
// then: rec pos sum (3), rec chain counts (MAXC),
//       pocket rp sum (3), pocket cross(rp,ref) sum (3)
#define ACC_CH(c,f) ((c)*7+(f))
#define ACC_RSUM  (MAXC*7)
#define ACC_RCNT  (MAXC*7+3)
#define ACC_PRP   (MAXC*7+3+MAXC)
#define ACC_PCR   (MAXC*7+6+MAXC)
#define ACC_N     (MAXC*7+9+MAXC)

__device__ double g_acc[ACC_N];
// float params: bt[MAXC*3], origin[3], fm[3], tm[3]
#define PAR_BT 0
#define PAR_OR (MAXC*3)
#define PAR_FM (MAXC*3+3)
#define PAR_TM (MAXC*3+6)
#define PAR_N  (MAXC*3+9)
__device__ float g_par[PAR_N];
__device__ float4 g_recpos[REC_CAP];  // xyz = positions[rec_indices[i]], w = chain id (bits)

__device__ __forceinline__ float warp_sum(float v) {
#pragma unroll
    for (int o = 16; o; o >>= 1) v += __shfl_down_sync(0xffffffffu, v, o);
    return v;
}
__device__ __forceinline__ int warp_sum_i(int v) {
#pragma unroll
    for (int o = 16; o; o >>= 1) v += __shfl_down_sync(0xffffffffu, v, o);
    return v;
}

__global__ void k_init() {
    int t = threadIdx.x;
    if (t < ACC_N) g_acc[t] = 0.0;
}

// Pass A: gather positions[rec_indices], cache (with chain id in .w),
// global position sum + per-chain rec counts.
__global__ void k_rec_sum(const float* __restrict__ pos,
                          const int* __restrict__ rec_idx,
                          const int* __restrict__ cid,
                          int n_rec, int C) {
    __shared__ float sf[3];
    __shared__ int   si[MAXC];
    if (threadIdx.x < 3) sf[threadIdx.x] = 0.f;
    if (threadIdx.x < C) si[threadIdx.x] = 0;
    __syncthreads();

    float px = 0.f, py = 0.f, pz = 0.f;
    int cnt[MAXC];
#pragma unroll
    for (int c = 0; c < MAXC; ++c) cnt[c] = 0;

    int stride = gridDim.x * blockDim.x;
    for (int i = blockIdx.x * blockDim.x + threadIdx.x; i < n_rec && i < REC_CAP; i += stride) {
        int r = __ldg(rec_idx + i);
        float x = __ldg(pos + 3 * r);
        float y = __ldg(pos + 3 * r + 1);
        float z = __ldg(pos + 3 * r + 2);
        int c = __ldg(cid + i);
        g_recpos[i] = make_float4(x, y, z, __int_as_float(c));
        px += x; py += y; pz += z;
        if (c >= 0 && c < MAXC) cnt[c]++;
    }
    px = warp_sum(px); py = warp_sum(py); pz = warp_sum(pz);
    unsigned lane = threadIdx.x & 31u;
    if (lane == 0) {
        atomicAdd(&sf[0], px); atomicAdd(&sf[1], py); atomicAdd(&sf[2], pz);
    }
#pragma unroll
    for (int c = 0; c < MAXC; ++c) {
        if (c >= C) break;
        int w = warp_sum_i(cnt[c]);
        if (lane == 0 && w) atomicAdd(&si[c], w);
    }
    __syncthreads();
    if (threadIdx.x < 3) {
        float v = sf[threadIdx.x];
        if (v != 0.f) atomicAdd(&g_acc[ACC_RSUM + threadIdx.x], (double)v);
    }
    if (threadIdx.x < C) {
        int v = si[threadIdx.x];
        if (v) atomicAdd(&g_acc[ACC_RCNT + threadIdx.x], (double)v);
    }
}

// Pass B: all pocket sums in one pass.
//  per-chain: poc_glob sum (BUG-faithful gather from global positions),
//             ref sum, count   (shared atomics)
//  global:    sum rp (rec-gathered pocket pos), sum cross(rp, ref)  (registers)
__global__ void k_poc(const float* __restrict__ pos,
                      const float* __restrict__ refp,
                      const int* __restrict__ pidx,
                      const int* __restrict__ pcid,
                      int n_poc, int C) {
    __shared__ float s[MAXC * 7];
    __shared__ float sg[6];
    for (int t = threadIdx.x; t < C * 7; t += blockDim.x) s[t] = 0.f;
    if (threadIdx.x < 6) sg[threadIdx.x] = 0.f;
    __syncthreads();

    float rpx = 0.f, rpy = 0.f, rpz = 0.f;   // sum rp
    float crx = 0.f, cry = 0.f, crz = 0.f;   // sum cross(rp, ref)

    int stride = gridDim.x * blockDim.x;
    for (int j = blockIdx.x * blockDim.x + threadIdx.x; j < n_poc; j += stride) {
        int p = __ldg(pidx + j);
        int c = __ldg(pcid + j);
        float gx = __ldg(pos + 3 * p), gy = __ldg(pos + 3 * p + 1), gz = __ldg(pos + 3 * p + 2);
        float rx = __ldg(refp + 3 * j), ry = __ldg(refp + 3 * j + 1), rz = __ldg(refp + 3 * j + 2);
        float4 rp = g_recpos[p];
        rpx += rp.x; rpy += rp.y; rpz += rp.z;
        crx += rp.y * rz - rp.z * ry;
        cry += rp.z * rx - rp.x * rz;
        crz += rp.x * ry - rp.y * rx;
        int b = (c >= 0 && c < MAXC) ? c * 7 : 0;
        atomicAdd(&s[b + 0], gx);
        atomicAdd(&s[b + 1], gy);
        atomicAdd(&s[b + 2], gz);
        atomicAdd(&s[b + 3], rx);
        atomicAdd(&s[b + 4], ry);
        atomicAdd(&s[b + 5], rz);
        atomicAdd(&s[b + 6], 1.f);
    }
    rpx = warp_sum(rpx); rpy = warp_sum(rpy); rpz = warp_sum(rpz);
    crx = warp_sum(crx); cry = warp_sum(cry); crz = warp_sum(crz);
    if ((threadIdx.x & 31u) == 0) {
        atomicAdd(&sg[0], rpx); atomicAdd(&sg[1], rpy); atomicAdd(&sg[2], rpz);
        atomicAdd(&sg[3], crx); atomicAdd(&sg[4], cry); atomicAdd(&sg[5], crz);
    }
    __syncthreads();
    for (int t = threadIdx.x; t < C * 7; t += blockDim.x) {
        float v = s[t];
        if (v != 0.f) atomicAdd(&g_acc[t], (double)v);
    }
    if (threadIdx.x < 6) {
        float v = sg[threadIdx.x];
        if (v != 0.f) {
            int dst = (threadIdx.x < 3) ? (ACC_PRP + threadIdx.x) : (ACC_PCR + threadIdx.x - 3);
            atomicAdd(&g_acc[dst], (double)v);
        }
    }
}

// Tiny kernel: parallel-load accumulators, then thread 0 computes bt, origin,
// F_mean and torque_mean analytically (no extra passes needed).
__global__ void k_setup(const float* __restrict__ box,
                        const float* __restrict__ kptr,
                        int C, int n_rec) {
    __shared__ double a[ACC_N];
    for (int t = threadIdx.x; t < ACC_N; t += blockDim.x) a[t] = g_acc[t];
    __syncthreads();
    if (threadIdx.x != 0) return;

    float r0x = box[0], r0y = box[1], r0z = box[2];
    float r1x = box[3], r1y = box[4], r1z = box[5];
    float r2x = box[6], r2y = box[7], r2z = box[8];
    float i0 = 1.f / box[0], i1 = 1.f / box[4], i2 = 1.f / box[8];
    float k2 = -2.f * *kptr;

    double otx = 0.0, oty = 0.0, otz = 0.0;     // sum rec_cnt_c * bt_c
    double fbx = 0.0, fby = 0.0, fbz = 0.0;     // sum poc_cnt_c * bt_c
    double tbx = 0.0, tby = 0.0, tbz = 0.0;     // sum cross(bt_c, refSum_c)

    for (int c = 0; c < C; ++c) {
        double cntd = a[ACC_CH(c, 6)];
        double inv = (cntd > 0.0) ? 1.0 / cntd : 0.0;
        float pcx = (float)(a[ACC_CH(c, 0)] * inv);
        float pcy = (float)(a[ACC_CH(c, 1)] * inv);
        float pcz = (float)(a[ACC_CH(c, 2)] * inv);
        double rsx = a[ACC_CH(c, 3)], rsy = a[ACC_CH(c, 4)], rsz = a[ACC_CH(c, 5)];
        float rcx = (float)(rsx * inv), rcy = (float)(rsy * inv), rcz = (float)(rsz * inv);
        // delta = ref_com - poc_com, reduce z, y, x sequentially
        float dx = rcx - pcx, dy = rcy - pcy, dz = rcz - pcz;
        float s3 = rintf(dz * i2);
        dx -= s3 * r2x; dy -= s3 * r2y; dz -= s3 * r2z;
        float s2 = rintf(dy * i1);
        dx -= s2 * r1x; dy -= s2 * r1y; dz -= s2 * r1z;
        float s1 = rintf(dx * i0);
        float tx = s1 * r0x + s2 * r1x + s3 * r2x;
        float ty = s1 * r0y + s2 * r1y + s3 * r2y;
        float tz = s1 * r0z + s2 * r1z + s3 * r2z;
        g_par[PAR_BT + c * 3 + 0] = tx;
        g_par[PAR_BT + c * 3 + 1] = ty;
        g_par[PAR_BT + c * 3 + 2] = tz;
        double rc = a[ACC_RCNT + c];
        otx += rc * tx; oty += rc * ty; otz += rc * tz;
        fbx += cntd * tx; fby += cntd * ty; fbz += cntd * tz;
        tbx += (double)ty * rsz - (double)tz * rsy;
        tby += (double)tz * rsx - (double)tx * rsz;
        tbz += (double)tx * rsy - (double)ty * rsx;
    }
    double invR = 1.0 / (double)n_rec;
    double ox = (a[ACC_RSUM + 0] + otx) * invR;
    double oy = (a[ACC_RSUM + 1] + oty) * invR;
    double oz = (a[ACC_RSUM + 2] + otz) * invR;
    g_par[PAR_OR + 0] = (float)ox;
    g_par[PAR_OR + 1] = (float)oy;
    g_par[PAR_OR + 2] = (float)oz;

    // total ref sum across chains
    double refx = 0.0, refy = 0.0, refz = 0.0;
    for (int c = 0; c < C; ++c) {
        refx += a[ACC_CH(c, 3)]; refy += a[ACC_CH(c, 4)]; refz += a[ACC_CH(c, 5)];
    }
    // F_sum = k2 * (sum rp - sum ref + sum_c cnt_c*bt_c)
    double Fx = (double)k2 * (a[ACC_PRP + 0] - refx + fbx);
    double Fy = (double)k2 * (a[ACC_PRP + 1] - refy + fby);
    double Fz = (double)k2 * (a[ACC_PRP + 2] - refz + fbz);
    // Tpos = -k2 * (sum cross(rp,ref) + sum_c cross(bt_c, refSum_c))
    double Tx = -(double)k2 * (a[ACC_PCR + 0] + tbx);
    double Ty = -(double)k2 * (a[ACC_PCR + 1] + tby);
    double Tz = -(double)k2 * (a[ACC_PCR + 2] + tbz);
    // T_sum = Tpos - cross(origin, F_sum)
    Tx -= oy * Fz - oz * Fy;
    Ty -= oz * Fx - ox * Fz;
    Tz -= ox * Fy - oy * Fx;

    g_par[PAR_FM + 0] = (float)(Fx * invR);
    g_par[PAR_FM + 1] = (float)(Fy * invR);
    g_par[PAR_FM + 2] = (float)(Fz * invR);
    g_par[PAR_TM + 0] = (float)(Tx * invR);
    g_par[PAR_TM + 1] = (float)(Ty * invR);
    g_par[PAR_TM + 2] = (float)(Tz * invR);
}

// Pass C: scatter final forces into output.
__global__ void k_scatter(const int* __restrict__ rec_idx,
                          float* __restrict__ out,
                          int n_rec, int base) {
    int i = blockIdx.x * blockDim.x + threadIdx.x;
    if (i >= n_rec || i >= REC_CAP) return;
    float4 rp = g_recpos[i];
    int c = __float_as_int(rp.w);
    int r = __ldg(rec_idx + i);
    float ox = g_par[PAR_OR + 0], oy = g_par[PAR_OR + 1], oz = g_par[PAR_OR + 2];
    float cx = rp.x + g_par[PAR_BT + c * 3 + 0] - ox;
    float cy = rp.y + g_par[PAR_BT + c * 3 + 1] - oy;
    float cz = rp.z + g_par[PAR_BT + c * 3 + 2] - oz;
    float inv = 1.f / (cx * cx + cy * cy + cz * cz);
    float tmx = g_par[PAR_TM + 0], tmy = g_par[PAR_TM + 1], tmz = g_par[PAR_TM + 2];
    float Fx = g_par[PAR_FM + 0] + (tmy * cz - tmz * cy) * inv;
    float Fy = g_par[PAR_FM + 1] + (tmz * cx - tmx * cz) * inv;
    float Fz = g_par[PAR_FM + 2] + (tmx * cy - tmy * cx) * inv;
    long long o = (long long)base + 3LL * (long long)r;
    out[o + 0] = Fx;
    out[o + 1] = Fy;
    out[o + 2] = Fz;
}

extern "C" void kernel_launch(void* const* d_in, const int* in_sizes, int n_in,
                              void* d_out, int out_size) {
    const float* positions = (const float*)d_in[0];
    const float* box       = (const float*)d_in[1];
    const float* ref_poc   = (const float*)d_in[2];
    const float* kptr      = (const float*)d_in[3];
    const int*   rec_idx   = (const int*)d_in[4];
    const int*   poc_idx   = (const int*)d_in[5];
    const int*   cid       = (const int*)d_in[6];
    const int*   pcid      = (const int*)d_in[7];

    int n_atoms = in_sizes[0] / 3;
    int n_rec   = in_sizes[4];
    int n_poc   = in_sizes[5];
    int base = out_size - 3 * n_atoms;
    if (base < 0) base = 0;
    const int C = MAXC > 4 ? 4 : MAXC;  // n_chains = 4 (scalar not passed as device data)

    const int TPB = 256;
    int blkA = (n_rec + TPB - 1) / TPB; if (blkA > 1184) blkA = 1184;
    int blkB = (n_poc + TPB - 1) / TPB; if (blkB > 1184) blkB = 1184;

    cudaMemsetAsync(d_out, 0, (size_t)out_size * sizeof(float));
    k_init<<<1, 128>>>();
    k_rec_sum<<<blkA, TPB>>>(positions, rec_idx, cid, n_rec, C);
    k_poc<<<blkB, TPB>>>(positions, ref_poc, poc_idx, pcid, n_poc, C);
    k_setup<<<1, 128>>>(box, kptr, C, n_rec);
    k_scatter<<<(n_rec + TPB - 1) / TPB, TPB>>>(rec_idx, (float*)d_out, n_rec, base);
}

// round 3
// speedup vs baseline: 1.5293x; 1.4237x over previous
#include <cuda_runtime.h>
#include <cuda_bf16.h>
#include <stdint.h>

#define MAXC 4
#define REC_CAP 2097152

// Accumulator layout (doubles):
// per chain c (7): 0..2 poc_glob sum, 3..5 ref sum, 6 count
// then: rec pos sum (3), rec chain counts (MAXC),
//       pocket rp sum (3), pocket cross(rp,ref) sum (3)
#define ACC_CH(c,f) ((c)*7+(f))
#define ACC_RSUM  (MAXC*7)
#define ACC_RCNT  (MAXC*7+3)
#define ACC_PRP   (MAXC*7+3+MAXC)
#define ACC_PCR   (MAXC*7+6+MAXC)
#define ACC_N     (MAXC*7+9+MAXC)

__device__ double g_acc[ACC_N];   // zero-initialized at load; k_setup re-zeroes after use
// float params: bt[MAXC*3], origin[3], fm[3], tm[3]
#define PAR_BT 0
#define PAR_OR (MAXC*3)
#define PAR_FM (MAXC*3+3)
#define PAR_TM (MAXC*3+6)
#define PAR_N  (MAXC*3+9)
__device__ float g_par[PAR_N];
__device__ float4 g_recpos[REC_CAP];  // xyz = positions[rec_indices[i]], w = chain id bits

__device__ __forceinline__ float warp_sum(float v) {
#pragma unroll
    for (int o = 16; o; o >>= 1) v += __shfl_down_sync(0xffffffffu, v, o);
    return v;
}
__device__ __forceinline__ int warp_sum_i(int v) {
#pragma unroll
    for (int o = 16; o; o >>= 1) v += __shfl_down_sync(0xffffffffu, v, o);
    return v;
}

// Pass A: gather positions[rec_indices], cache (with chain id in .w),
// global position sum + per-chain rec counts.
__global__ void k_rec_sum(const float* __restrict__ pos,
                          const int* __restrict__ rec_idx,
                          const int* __restrict__ cid,
                          int n_rec) {
    __shared__ float sf[3];
    __shared__ int   si[MAXC];
    if (threadIdx.x < 3) sf[threadIdx.x] = 0.f;
    if (threadIdx.x < MAXC) si[threadIdx.x] = 0;
    __syncthreads();

    float px = 0.f, py = 0.f, pz = 0.f;
    int cnt[MAXC];
#pragma unroll
    for (int c = 0; c < MAXC; ++c) cnt[c] = 0;

    int stride = gridDim.x * blockDim.x;
    for (int i = blockIdx.x * blockDim.x + threadIdx.x; i < n_rec && i < REC_CAP; i += stride) {
        int r = __ldg(rec_idx + i);
        float x = __ldg(pos + 3 * r);
        float y = __ldg(pos + 3 * r + 1);
        float z = __ldg(pos + 3 * r + 2);
        int c = __ldg(cid + i);
        g_recpos[i] = make_float4(x, y, z, __int_as_float(c));
        px += x; py += y; pz += z;
#pragma unroll
        for (int cc = 0; cc < MAXC; ++cc) if (c == cc) cnt[cc]++;
    }
    px = warp_sum(px); py = warp_sum(py); pz = warp_sum(pz);
    unsigned lane = threadIdx.x & 31u;
    if (lane == 0) {
        atomicAdd(&sf[0], px); atomicAdd(&sf[1], py); atomicAdd(&sf[2], pz);
    }
#pragma unroll
    for (int c = 0; c < MAXC; ++c) {
        int w = warp_sum_i(cnt[c]);
        if (lane == 0 && w) atomicAdd(&si[c], w);
    }
    __syncthreads();
    if (threadIdx.x < 3) {
        float v = sf[threadIdx.x];
        if (v != 0.f) atomicAdd(&g_acc[ACC_RSUM + threadIdx.x], (double)v);
    }
    if (threadIdx.x < MAXC) {
        int v = si[threadIdx.x];
        if (v) atomicAdd(&g_acc[ACC_RCNT + threadIdx.x], (double)v);
    }
}

// Pass B: all pocket sums in one pass, register-accumulated.
//  per-chain: poc_glob sum (BUG-faithful gather from global positions),
//             ref sum, count
//  global:    sum rp (rec-gathered pocket pos), sum cross(rp, ref)
__global__ void k_poc(const float* __restrict__ pos,
                      const float* __restrict__ refp,
                      const int* __restrict__ pidx,
                      const int* __restrict__ pcid,
                      int n_poc) {
    __shared__ float s[MAXC * 7 + 6];
    for (int t = threadIdx.x; t < MAXC * 7 + 6; t += blockDim.x) s[t] = 0.f;
    __syncthreads();

    // per-chain register accumulators
    float a[MAXC][6];
    int   an[MAXC];
#pragma unroll
    for (int c = 0; c < MAXC; ++c) {
#pragma unroll
        for (int f = 0; f < 6; ++f) a[c][f] = 0.f;
        an[c] = 0;
    }
    float rpx = 0.f, rpy = 0.f, rpz = 0.f;   // sum rp
    float crx = 0.f, cry = 0.f, crz = 0.f;   // sum cross(rp, ref)

    int stride = gridDim.x * blockDim.x;
    for (int j = blockIdx.x * blockDim.x + threadIdx.x; j < n_poc; j += stride) {
        int p = __ldg(pidx + j);
        int c = __ldg(pcid + j);
        float gx = __ldg(pos + 3 * p), gy = __ldg(pos + 3 * p + 1), gz = __ldg(pos + 3 * p + 2);
        float rx = __ldg(refp + 3 * j), ry = __ldg(refp + 3 * j + 1), rz = __ldg(refp + 3 * j + 2);
        float4 rp = g_recpos[p];
        rpx += rp.x; rpy += rp.y; rpz += rp.z;
        crx += rp.y * rz - rp.z * ry;
        cry += rp.z * rx - rp.x * rz;
        crz += rp.x * ry - rp.y * rx;
#pragma unroll
        for (int cc = 0; cc < MAXC; ++cc) {
            if (c == cc) {
                a[cc][0] += gx; a[cc][1] += gy; a[cc][2] += gz;
                a[cc][3] += rx; a[cc][4] += ry; a[cc][5] += rz;
                an[cc]++;
            }
        }
    }
    unsigned lane = threadIdx.x & 31u;
#pragma unroll
    for (int c = 0; c < MAXC; ++c) {
#pragma unroll
        for (int f = 0; f < 6; ++f) {
            float w = warp_sum(a[c][f]);
            if (lane == 0 && w != 0.f) atomicAdd(&s[c * 7 + f], w);
        }
        int w = warp_sum_i(an[c]);
        if (lane == 0 && w) atomicAdd(&s[c * 7 + 6], (float)w);
    }
    rpx = warp_sum(rpx); rpy = warp_sum(rpy); rpz = warp_sum(rpz);
    crx = warp_sum(crx); cry = warp_sum(cry); crz = warp_sum(crz);
    if (lane == 0) {
        atomicAdd(&s[MAXC * 7 + 0], rpx); atomicAdd(&s[MAXC * 7 + 1], rpy);
        atomicAdd(&s[MAXC * 7 + 2], rpz); atomicAdd(&s[MAXC * 7 + 3], crx);
        atomicAdd(&s[MAXC * 7 + 4], cry); atomicAdd(&s[MAXC * 7 + 5], crz);
    }
    __syncthreads();
    for (int t = threadIdx.x; t < MAXC * 7 + 6; t += blockDim.x) {
        float v = s[t];
        if (v != 0.f) {
            int dst = (t < MAXC * 7) ? t
                     : (t < MAXC * 7 + 3 ? ACC_PRP + (t - MAXC * 7)
                                         : ACC_PCR + (t - MAXC * 7 - 3));
            atomicAdd(&g_acc[dst], (double)v);
        }
    }
}

// Tiny kernel: parallel-stage all scalars into shared, thread 0 computes
// bt, origin, F_mean, torque_mean analytically. Re-zeroes g_acc at the end.
__global__ void k_setup(const float* __restrict__ box,
                        const float* __restrict__ kptr,
                        int n_rec) {
    __shared__ double a[ACC_N];
    __shared__ float  sb[10];   // box[9], k
    int t = threadIdx.x;
    if (t < ACC_N) a[t] = g_acc[t];
    if (t >= 64 && t < 73) sb[t - 64] = box[t - 64];
    if (t == 73) sb[9] = *kptr;
    __syncthreads();
    if (t < ACC_N) g_acc[t] = 0.0;   // reset for next graph replay
    if (t != 0) return;

    float r0x = sb[0], r0y = sb[1], r0z = sb[2];
    float r1x = sb[3], r1y = sb[4], r1z = sb[5];
    float r2x = sb[6], r2y = sb[7], r2z = sb[8];
    float i0 = 1.f / sb[0], i1 = 1.f / sb[4], i2 = 1.f / sb[8];
    float k2 = -2.f * sb[9];

    double otx = 0.0, oty = 0.0, otz = 0.0;     // sum rec_cnt_c * bt_c
    double fbx = 0.0, fby = 0.0, fbz = 0.0;     // sum poc_cnt_c * bt_c
    double tbx = 0.0, tby = 0.0, tbz = 0.0;     // sum cross(bt_c, refSum_c)
    double refx = 0.0, refy = 0.0, refz = 0.0;

#pragma unroll
    for (int c = 0; c < MAXC; ++c) {
        double cntd = a[ACC_CH(c, 6)];
        double inv = (cntd > 0.0) ? 1.0 / cntd : 0.0;
        float pcx = (float)(a[ACC_CH(c, 0)] * inv);
        float pcy = (float)(a[ACC_CH(c, 1)] * inv);
        float pcz = (float)(a[ACC_CH(c, 2)] * inv);
        double rsx = a[ACC_CH(c, 3)], rsy = a[ACC_CH(c, 4)], rsz = a[ACC_CH(c, 5)];
        refx += rsx; refy += rsy; refz += rsz;
        float rcx = (float)(rsx * inv), rcy = (float)(rsy * inv), rcz = (float)(rsz * inv);
        // delta = ref_com - poc_com, reduce z, y, x sequentially
        float dx = rcx - pcx, dy = rcy - pcy, dz = rcz - pcz;
        float s3 = rintf(dz * i2);
        dx -= s3 * r2x; dy -= s3 * r2y; dz -= s3 * r2z;
        float s2 = rintf(dy * i1);
        dx -= s2 * r1x; dy -= s2 * r1y; dz -= s2 * r1z;
        float s1 = rintf(dx * i0);
        float tx = s1 * r0x + s2 * r1x + s3 * r2x;
        float ty = s1 * r0y + s2 * r1y + s3 * r2y;
        float tz = s1 * r0z + s2 * r1z + s3 * r2z;
        g_par[PAR_BT + c * 3 + 0] = tx;
        g_par[PAR_BT + c * 3 + 1] = ty;
        g_par[PAR_BT + c * 3 + 2] = tz;
        double rc = a[ACC_RCNT + c];
        otx += rc * tx; oty += rc * ty; otz += rc * tz;
        fbx += cntd * tx; fby += cntd * ty; fbz += cntd * tz;
        tbx += (double)ty * rsz - (double)tz * rsy;
        tby += (double)tz * rsx - (double)tx * rsz;
        tbz += (double)tx * rsy - (double)ty * rsx;
    }
    double invR = 1.0 / (double)n_rec;
    double ox = (a[ACC_RSUM + 0] + otx) * invR;
    double oy = (a[ACC_RSUM + 1] + oty) * invR;
    double oz = (a[ACC_RSUM + 2] + otz) * invR;
    g_par[PAR_OR + 0] = (float)ox;
    g_par[PAR_OR + 1] = (float)oy;
    g_par[PAR_OR + 2] = (float)oz;

    // F_sum = k2 * (sum rp - sum ref + sum_c cnt_c*bt_c)
    double Fx = (double)k2 * (a[ACC_PRP + 0] - refx + fbx);
    double Fy = (double)k2 * (a[ACC_PRP + 1] - refy + fby);
    double Fz = (double)k2 * (a[ACC_PRP + 2] - refz + fbz);
    // Tpos = -k2 * (sum cross(rp,ref) + sum_c cross(bt_c, refSum_c))
    double Tx = -(double)k2 * (a[ACC_PCR + 0] + tbx);
    double Ty = -(double)k2 * (a[ACC_PCR + 1] + tby);
    double Tz = -(double)k2 * (a[ACC_PCR + 2] + tbz);
    // T_sum = Tpos - cross(origin, F_sum)
    Tx -= oy * Fz - oz * Fy;
    Ty -= oz * Fx - ox * Fz;
    Tz -= ox * Fy - oy * Fx;

    g_par[PAR_FM + 0] = (float)(Fx * invR);
    g_par[PAR_FM + 1] = (float)(Fy * invR);
    g_par[PAR_FM + 2] = (float)(Fz * invR);
    g_par[PAR_TM + 0] = (float)(Tx * invR);
    g_par[PAR_TM + 1] = (float)(Ty * invR);
    g_par[PAR_TM + 2] = (float)(Tz * invR);
}

// Pass C: scatter final forces into output (memset'd just before, so the
// touched lines are L2-resident and the partial writes merge).
__global__ void k_scatter(const int* __restrict__ rec_idx,
                          float* __restrict__ out,
                          int n_rec, int base) {
    int i = blockIdx.x * blockDim.x + threadIdx.x;
    if (i >= n_rec || i >= REC_CAP) return;
    float4 rp = g_recpos[i];
    int c = __float_as_int(rp.w);
    int r = __ldg(rec_idx + i);
    float ox = g_par[PAR_OR + 0], oy = g_par[PAR_OR + 1], oz = g_par[PAR_OR + 2];
    float cx = rp.x + g_par[PAR_BT + c * 3 + 0] - ox;
    float cy = rp.y + g_par[PAR_BT + c * 3 + 1] - oy;
    float cz = rp.z + g_par[PAR_BT + c * 3 + 2] - oz;
    float inv = 1.f / (cx * cx + cy * cy + cz * cz);
    float tmx = g_par[PAR_TM + 0], tmy = g_par[PAR_TM + 1], tmz = g_par[PAR_TM + 2];
    float Fx = g_par[PAR_FM + 0] + (tmy * cz - tmz * cy) * inv;
    float Fy = g_par[PAR_FM + 1] + (tmz * cx - tmx * cz) * inv;
    float Fz = g_par[PAR_FM + 2] + (tmx * cy - tmy * cx) * inv;
    long long o = (long long)base + 3LL * (long long)r;
    out[o + 0] = Fx;
    out[o + 1] = Fy;
    out[o + 2] = Fz;
}

extern "C" void kernel_launch(void* const* d_in, const int* in_sizes, int n_in,
                              void* d_out, int out_size) {
    const float* positions = (const float*)d_in[0];
    const float* box       = (const float*)d_in[1];
    const float* ref_poc   = (const float*)d_in[2];
    const float* kptr      = (const float*)d_in[3];
    const int*   rec_idx   = (const int*)d_in[4];
    const int*   poc_idx   = (const int*)d_in[5];
    const int*   cid       = (const int*)d_in[6];
    const int*   pcid      = (const int*)d_in[7];

    int n_atoms = in_sizes[0] / 3;
    int n_rec   = in_sizes[4];
    int n_poc   = in_sizes[5];
    int base = out_size - 3 * n_atoms;
    if (base < 0) base = 0;

    const int TPB = 256;
    int blkA = (n_rec + TPB - 1) / TPB; if (blkA > 1184) blkA = 1184;
    int blkB = (n_poc + TPB - 1) / TPB; if (blkB > 296) blkB = 296;

    k_rec_sum<<<blkA, TPB>>>(positions, rec_idx, cid, n_rec);
    k_poc<<<blkB, TPB>>>(positions, ref_poc, poc_idx, pcid, n_poc);
    k_setup<<<1, 128>>>(box, kptr, n_rec);
    // memset here (not first): output lines are L2-hot when the scatter hits them
    cudaMemsetAsync(d_out, 0, (size_t)out_size * sizeof(float));
    k_scatter<<<(n_rec + TPB - 1) / TPB, TPB>>>(rec_idx, (float*)d_out, n_rec, base);
}